// round 10
// baseline (speedup 1.0000x reference)
#include <cuda_runtime.h>
#include <cuda_fp16.h>
#include <cstdint>

#define HID 128
#define NN 50000
#define NE 800000
// byte strides (all ≡16 mod 128 -> ldmatrix conflict-free)
#define SA_STR 272   // A tiles: 136 halves/row
#define EW_STR 144   // eWt  [128 x 64k]
#define W1_STR 528   // W1t  [128 x 256k]
#define W2_STR 272   // W2t  [128 x 128k]

extern __shared__ char dyn_smem[];

// ---------------- device scratch (allocation-free rule) ----------------
__device__ __half g_h[(size_t)NN * HID];   // node embeddings (fp16)
__device__ float  g_agg[(size_t)NN * HID]; // segment-sum accumulator (fp32)
__device__ __half g_nWt[128 * 128];        // node_W^T  [N][K] fp16
__device__ __half g_eWt[128 * 64];         // edge_W^T
__device__ __half g_W1t[128 * 256];        // msg_W1^T
__device__ __half g_W2t[128 * 128];        // msg_W2^T
__device__ __half g_U1t[128 * 256];        // upd_W1^T
__device__ __half g_U2t[128 * 128];        // upd_W2^T

// ======================= helpers (generic PTX) =========================
__device__ __forceinline__ uint32_t smem_u32(const void* p) {
    uint32_t a;
    asm("{ .reg .u64 t; cvta.to.shared.u64 t, %1; cvt.u32.u64 %0, t; }"
        : "=r"(a) : "l"(p));
    return a;
}
__device__ __forceinline__ void ldsm4(uint32_t r[4], uint32_t addr) {
    asm volatile("ldmatrix.sync.aligned.m8n8.x4.shared.b16 {%0,%1,%2,%3}, [%4];"
                 : "=r"(r[0]), "=r"(r[1]), "=r"(r[2]), "=r"(r[3]) : "r"(addr));
}
__device__ __forceinline__ void mma16(float c[4], const uint32_t a[4],
                                      uint32_t b0, uint32_t b1) {
    asm volatile("mma.sync.aligned.m16n8k16.row.col.f32.f16.f16.f32 "
                 "{%0,%1,%2,%3}, {%4,%5,%6,%7}, {%8,%9}, {%0,%1,%2,%3};"
                 : "+f"(c[0]), "+f"(c[1]), "+f"(c[2]), "+f"(c[3])
                 : "r"(a[0]), "r"(a[1]), "r"(a[2]), "r"(a[3]), "r"(b0), "r"(b1));
}
#define CP16(dst, src) \
    asm volatile("cp.async.cg.shared.global [%0], [%1], 16;" :: "r"(dst), "l"(src))
#define CP_COMMIT() asm volatile("cp.async.commit_group;" ::: "memory")
#define CP_WAIT(n)  asm volatile("cp.async.wait_group %0;" :: "n"(n) : "memory")

__device__ __forceinline__ void zacc(float acc[2][4][4]) {
#pragma unroll
    for (int i = 0; i < 2; ++i)
#pragma unroll
        for (int j = 0; j < 4; ++j)
#pragma unroll
            for (int k = 0; k < 4; ++k) acc[i][j][k] = 0.f;
}

// Warp GEMM: 32x32 output tile, KSTEPS k-steps of 16 (32B each).
// A rows stride SA_STR; B rows stride bStr.
template <int KSTEPS>
__device__ __forceinline__ void wgemm(uint32_t aA0, uint32_t aA1,
                                      const uint32_t bA[2], float acc[2][4][4]) {
#pragma unroll
    for (int ks = 0; ks < KSTEPS; ++ks) {
        uint32_t a0[4], a1[4];
        ldsm4(a0, aA0 + ks * 32);
        ldsm4(a1, aA1 + ks * 32);
#pragma unroll
        for (int jj = 0; jj < 2; ++jj) {
            uint32_t b[4];
            ldsm4(b, bA[jj] + ks * 32);
            mma16(acc[0][2 * jj],     a0, b[0], b[1]);
            mma16(acc[0][2 * jj + 1], a0, b[2], b[3]);
            mma16(acc[1][2 * jj],     a1, b[0], b[1]);
            mma16(acc[1][2 * jj + 1], a1, b[2], b[3]);
        }
    }
}

__device__ __forceinline__ uint32_t a_off(int lane, int strideB) {
    int row = (lane & 7) + ((lane & 8) ? 8 : 0);
    return (uint32_t)row * strideB + ((lane & 16) ? 16 : 0);
}
__device__ __forceinline__ uint32_t b_off(int lane, int strideB) {
    int row = (lane & 7) + ((lane & 16) ? 8 : 0);
    return (uint32_t)row * strideB + ((lane & 8) ? 16 : 0);
}

// cp.async a [128n x K] fp16 weight tile (src row stride srcK halves,
// dst row stride dstStr bytes), K halves per row = kh
template <int KH>
__device__ __forceinline__ void stage_w(uint32_t dstB, int dstStr,
                                        const __half* srcBase, int srcK, int tid) {
    constexpr int SEGS = KH / 8;  // 16B segments per row
#pragma unroll
    for (int i = tid; i < 128 * SEGS; i += 512) {
        int n = i / SEGS, s = i % SEGS;
        CP16(dstB + (uint32_t)(n * dstStr + s * 16),
             srcBase + (size_t)n * srcK + s * 8);
    }
}

// ---------------------------------------------------------------------------
// Prep: transpose + fp16-convert all weight matrices
// ---------------------------------------------------------------------------
__global__ void k_tW(const float* __restrict__ nW, const float* __restrict__ eW,
                     const float* __restrict__ W1, const float* __restrict__ W2,
                     const float* __restrict__ U1, const float* __restrict__ U2) {
    int t = blockIdx.x * blockDim.x + threadIdx.x;
    int tot = gridDim.x * blockDim.x;
    for (int i = t; i < 128 * 128; i += tot) {
        int n = i >> 7, k = i & 127;
        g_nWt[i] = __float2half_rn(nW[k * 128 + n]);
        g_W2t[i] = __float2half_rn(W2[k * 128 + n]);
        g_U2t[i] = __float2half_rn(U2[k * 128 + n]);
    }
    for (int i = t; i < 128 * 64; i += tot) {
        int n = i >> 6, k = i & 63;
        g_eWt[i] = __float2half_rn(eW[k * 128 + n]);
    }
    for (int i = t; i < 128 * 256; i += tot) {
        int n = i >> 8, k = i & 255;
        g_W1t[i] = __float2half_rn(W1[k * 128 + n]);
        g_U1t[i] = __float2half_rn(U1[k * 128 + n]);
    }
}

__global__ __launch_bounds__(256) void k_zero_agg() {
    size_t i = (size_t)blockIdx.x * 256 + threadIdx.x;
    reinterpret_cast<float4*>(g_agg)[i] = make_float4(0.f, 0.f, 0.f, 0.f);
}

// ---------------------------------------------------------------------------
// Kernel 1: h = fp16(node_feats @ node_W + node_b) -> g_h  (128 rows/block)
// ---------------------------------------------------------------------------
static constexpr int NODE_SA = 0;
static constexpr int NODE_SB = 128 * SA_STR;
static constexpr int NODE_BIAS = NODE_SB + 128 * SA_STR;
static constexpr int NODE_SMEM = NODE_BIAS + 512;

__global__ __launch_bounds__(512, 1) void k_node(const float* __restrict__ nf,
                                                 const float* __restrict__ b) {
    char* smem = dyn_smem;
    float* sBias = reinterpret_cast<float*>(smem + NODE_BIAS);
    const uint32_t sb0 = smem_u32(smem);
    const int tid = threadIdx.x, lane = tid & 31, w = tid >> 5;
    const int base = blockIdx.x * 128;

    if (tid < 128) sBias[tid] = b[tid];
    for (int i = tid; i < 128 * 32; i += 512) {
        int r = i >> 5, c = (i & 31) * 4;
        int gr = base + r;
        float4 v = make_float4(0.f, 0.f, 0.f, 0.f);
        if (gr < NN) v = *reinterpret_cast<const float4*>(nf + (size_t)gr * HID + c);
        __half2* p = reinterpret_cast<__half2*>(smem + NODE_SA + r * SA_STR + c * 2);
        p[0] = __floats2half2_rn(v.x, v.y);
        p[1] = __floats2half2_rn(v.z, v.w);
    }
    for (int i = tid; i < 128 * 16; i += 512) {
        int r = i >> 4, s = (i & 15);
        *reinterpret_cast<float4*>(smem + NODE_SB + r * SA_STR + s * 16) =
            *reinterpret_cast<const float4*>(
                reinterpret_cast<const char*>(g_nWt) + (size_t)r * 256 + s * 16);
    }
    __syncthreads();

    const int mb = (w & 3) * 32, nb = (w >> 2) * 32;
    uint32_t aA0 = sb0 + NODE_SA + (uint32_t)mb * SA_STR + a_off(lane, SA_STR);
    uint32_t aA1 = aA0 + 16 * SA_STR;
    uint32_t bA[2];
#pragma unroll
    for (int jj = 0; jj < 2; ++jj)
        bA[jj] = sb0 + NODE_SB + (uint32_t)(nb + jj * 16) * SA_STR + b_off(lane, SA_STR);

    float acc[2][4][4];
    zacc(acc);
    wgemm<8>(aA0, aA1, bA, acc);  // K = 128

    const int g = lane >> 2, tg = lane & 3;
#pragma unroll
    for (int i = 0; i < 2; ++i) {
        int r0 = base + mb + i * 16 + g;
#pragma unroll
        for (int j = 0; j < 4; ++j) {
            int c = nb + j * 8 + 2 * tg;
            if (r0 < NN)
                *reinterpret_cast<__half2*>(g_h + (size_t)r0 * HID + c) =
                    __floats2half2_rn(acc[i][j][0] + sBias[c], acc[i][j][1] + sBias[c + 1]);
            if (r0 + 8 < NN)
                *reinterpret_cast<__half2*>(g_h + (size_t)(r0 + 8) * HID + c) =
                    __floats2half2_rn(acc[i][j][2] + sBias[c], acc[i][j][3] + sBias[c + 1]);
        }
    }
}

// ---------------------------------------------------------------------------
// Kernel 2: fused edge pipeline, fp16, ALL weights resident in smem.
// smem: sH 34816 | sE 34816 | eW 18432 | W1 67584 | W2 34816 | misc
// ---------------------------------------------------------------------------
static constexpr int SH_B  = 0;
static constexpr int SE_B  = 128 * SA_STR;             // 34816
static constexpr int EW_B  = SE_B * 2;                 // 69632
static constexpr int W1_B  = EW_B + 128 * EW_STR;      // 88064
static constexpr int W2_B  = W1_B + 128 * W1_STR;      // 155648
static constexpr int MISC_B = W2_B + 128 * W2_STR;     // 190464
static constexpr int EDGE_SMEM = MISC_B + 4 * 128 * 4; // 192512

__global__ __launch_bounds__(512, 1) void k_edge(const int* __restrict__ eidx,
                                                 const float* __restrict__ ef,
                                                 const float* __restrict__ eb,
                                                 const float* __restrict__ b1,
                                                 const float* __restrict__ b2) {
    char* smem = dyn_smem;
    float* sEB = reinterpret_cast<float*>(smem + MISC_B);
    float* sB1b = sEB + 128;
    float* sB2b = sB1b + 128;
    int* sDst = reinterpret_cast<int*>(sB2b + 128);
    const uint32_t sb0 = smem_u32(smem);

    const int tid = threadIdx.x, lane = tid & 31, w = tid >> 5;
    const int e0 = blockIdx.x * 128;

    if (tid < 128) {
        sDst[tid] = eidx[NE + e0 + tid];
        sEB[tid] = eb[tid];
    } else if (tid < 256) {
        sB1b[tid - 128] = b1[tid - 128];
        sB2b[tid - 128] = b2[tid - 128];
    }

    // group0: eWt (needed by GEMM0)
    stage_w<64>(sb0 + EW_B, EW_STR, g_eWt, 64, tid);
    CP_COMMIT();
    // group1: gather h[src] -> sH ; W1t ; W2t (needed from GEMM1 on)
#pragma unroll
    for (int i = tid; i < 128 * 16; i += 512) {
        int r = i >> 4, s = i & 15;
        int src = eidx[e0 + r];
        CP16(sb0 + SH_B + (uint32_t)(r * SA_STR + s * 16),
             g_h + (size_t)src * HID + s * 8);
    }
    stage_w<256>(sb0 + W1_B, W1_STR, g_W1t, 256, tid);
    stage_w<128>(sb0 + W2_B, W2_STR, g_W2t, 128, tid);
    CP_COMMIT();

    // ef [128x64] fp32 -> fp16 into sE cols 0..63
#pragma unroll
    for (int i = tid; i < 128 * 16; i += 512) {
        int r = i >> 4, c = (i & 15) * 4;
        float4 v = *reinterpret_cast<const float4*>(ef + (size_t)(e0 + r) * 64 + c);
        __half2* p = reinterpret_cast<__half2*>(smem + SE_B + r * SA_STR + c * 2);
        p[0] = __floats2half2_rn(v.x, v.y);
        p[1] = __floats2half2_rn(v.z, v.w);
    }

    const int mb = (w & 3) * 32, nb = (w >> 2) * 32;
    uint32_t aH0 = sb0 + SH_B + (uint32_t)mb * SA_STR + a_off(lane, SA_STR);
    uint32_t aH1 = aH0 + 16 * SA_STR;
    uint32_t aE0 = sb0 + SE_B + (uint32_t)mb * SA_STR + a_off(lane, SA_STR);
    uint32_t aE1 = aE0 + 16 * SA_STR;
    uint32_t bEW[2], bW1[2], bW2[2];
#pragma unroll
    for (int jj = 0; jj < 2; ++jj) {
        int nrow = nb + jj * 16;
        bEW[jj] = sb0 + EW_B + (uint32_t)nrow * EW_STR + b_off(lane, EW_STR);
        bW1[jj] = sb0 + W1_B + (uint32_t)nrow * W1_STR + b_off(lane, W1_STR);
        bW2[jj] = sb0 + W2_B + (uint32_t)nrow * W2_STR + b_off(lane, W2_STR);
    }

    const int g = lane >> 2, tg = lane & 3;
    float acc[2][4][4];

    // ---- GEMM0: e = ef @ eWt (K=64) ----
    CP_WAIT(1);          // eWt complete (gather/W1/W2 may still fly)
    __syncthreads();     // publish eWt + ef + biases
    zacc(acc);
    wgemm<4>(aE0, aE1, bEW, acc);

    CP_WAIT(0);          // gather + W1 + W2 complete
    __syncthreads();     // publish sH/W1/W2; WAR: sE(ef) reads done
    // epilogue0: e = acc + eb -> sE (fp16, full 128 cols)
#pragma unroll
    for (int i = 0; i < 2; ++i) {
        int r0 = mb + i * 16 + g;
#pragma unroll
        for (int j = 0; j < 4; ++j) {
            int c = nb + j * 8 + 2 * tg;
            *reinterpret_cast<__half2*>(smem + SE_B + r0 * SA_STR + c * 2) =
                __floats2half2_rn(acc[i][j][0] + sEB[c], acc[i][j][1] + sEB[c + 1]);
            *reinterpret_cast<__half2*>(smem + SE_B + (r0 + 8) * SA_STR + c * 2) =
                __floats2half2_rn(acc[i][j][2] + sEB[c], acc[i][j][3] + sEB[c + 1]);
        }
    }
    __syncthreads();     // publish e

    // ---- GEMM1: t = relu([h|e] @ W1t + b1), K=256, no intervening barriers ----
    zacc(acc);
    wgemm<8>(aH0, aH1, bW1, acc);                       // h x W1[:, 0:128]
    {
        uint32_t bW1hi[2] = {bW1[0] + 256, bW1[1] + 256};
        wgemm<8>(aE0, aE1, bW1hi, acc);                 // e x W1[:, 128:256]
    }
    __syncthreads();     // GEMM1 sH reads done (WAR before epilogue1)

    // epilogue1: t = relu(acc + b1) -> sH (fp16)
#pragma unroll
    for (int i = 0; i < 2; ++i) {
        int r0 = mb + i * 16 + g;
#pragma unroll
        for (int j = 0; j < 4; ++j) {
            int c = nb + j * 8 + 2 * tg;
            *reinterpret_cast<__half2*>(smem + SH_B + r0 * SA_STR + c * 2) =
                __floats2half2_rn(fmaxf(acc[i][j][0] + sB1b[c], 0.f),
                                  fmaxf(acc[i][j][1] + sB1b[c + 1], 0.f));
            *reinterpret_cast<__half2*>(smem + SH_B + (r0 + 8) * SA_STR + c * 2) =
                __floats2half2_rn(fmaxf(acc[i][j][2] + sB1b[c], 0.f),
                                  fmaxf(acc[i][j][3] + sB1b[c + 1], 0.f));
        }
    }
    __syncthreads();     // publish t

    // ---- GEMM2: m = t @ W2t + b2 (K=128) ----
    zacc(acc);
    wgemm<8>(aH0, aH1, bW2, acc);

    // scatter-add into g_agg[dst]
#pragma unroll
    for (int i = 0; i < 2; ++i) {
        int r0 = mb + i * 16 + g;
        float* p0 = g_agg + (size_t)sDst[r0] * HID;
        float* p1 = g_agg + (size_t)sDst[r0 + 8] * HID;
#pragma unroll
        for (int j = 0; j < 4; ++j) {
            int c = nb + j * 8 + 2 * tg;
            atomicAdd(p0 + c, acc[i][j][0] + sB2b[c]);
            atomicAdd(p0 + c + 1, acc[i][j][1] + sB2b[c + 1]);
            atomicAdd(p1 + c, acc[i][j][2] + sB2b[c]);
            atomicAdd(p1 + c + 1, acc[i][j][3] + sB2b[c + 1]);
        }
    }
}

// ---------------------------------------------------------------------------
// Kernel 3: out = relu([nf|agg] @ U1 + ub1) @ U2 + ub2   (fp16 MMA, fp32 out)
// All weights resident: sH | sE | U1 (528B str) | U2 (272B str) | biases
// ---------------------------------------------------------------------------
static constexpr int UPD_SH = 0;
static constexpr int UPD_SE = 128 * SA_STR;
static constexpr int UPD_U1 = 2 * 128 * SA_STR;            // 69632
static constexpr int UPD_U2 = UPD_U1 + 128 * W1_STR;       // 137216
static constexpr int UPD_B1 = UPD_U2 + 128 * W2_STR;       // 172032
static constexpr int UPD_B2 = UPD_B1 + 512;
static constexpr int UPD_SMEM = UPD_B2 + 512;

__global__ __launch_bounds__(512, 1) void k_update(const float* __restrict__ nf,
                                                   const float* __restrict__ b1,
                                                   const float* __restrict__ b2,
                                                   float* __restrict__ out) {
    char* smem = dyn_smem;
    float* sB1 = reinterpret_cast<float*>(smem + UPD_B1);
    float* sB2 = reinterpret_cast<float*>(smem + UPD_B2);
    const uint32_t sb0 = smem_u32(smem);

    const int tid = threadIdx.x, lane = tid & 31, w = tid >> 5;
    const int base = blockIdx.x * 128;

    if (tid < 128) {
        sB1[tid] = b1[tid];
        sB2[tid] = b2[tid];
    }
    // weights via cp.async (overlap with A-tile conversion)
    stage_w<256>(sb0 + UPD_U1, W1_STR, g_U1t, 256, tid);
    stage_w<128>(sb0 + UPD_U2, W2_STR, g_U2t, 128, tid);
    CP_COMMIT();

    // A tiles: nf -> sH, agg -> sE (fp32 -> fp16)
    for (int i = tid; i < 128 * 32; i += 512) {
        int r = i >> 5, c = (i & 31) * 4;
        int gr = base + r;
        float4 v0 = make_float4(0.f, 0.f, 0.f, 0.f), v1 = v0;
        if (gr < NN) {
            v0 = *reinterpret_cast<const float4*>(nf + (size_t)gr * HID + c);
            v1 = *reinterpret_cast<const float4*>(g_agg + (size_t)gr * HID + c);
        }
        __half2* p0 = reinterpret_cast<__half2*>(smem + UPD_SH + r * SA_STR + c * 2);
        p0[0] = __floats2half2_rn(v0.x, v0.y);
        p0[1] = __floats2half2_rn(v0.z, v0.w);
        __half2* p1 = reinterpret_cast<__half2*>(smem + UPD_SE + r * SA_STR + c * 2);
        p1[0] = __floats2half2_rn(v1.x, v1.y);
        p1[1] = __floats2half2_rn(v1.z, v1.w);
    }
    CP_WAIT(0);
    __syncthreads();

    const int mb = (w & 3) * 32, nb = (w >> 2) * 32;
    uint32_t aH0 = sb0 + UPD_SH + (uint32_t)mb * SA_STR + a_off(lane, SA_STR);
    uint32_t aH1 = aH0 + 16 * SA_STR;
    uint32_t aE0 = sb0 + UPD_SE + (uint32_t)mb * SA_STR + a_off(lane, SA_STR);
    uint32_t aE1 = aE0 + 16 * SA_STR;
    uint32_t bU1[2], bU2[2];
#pragma unroll
    for (int jj = 0; jj < 2; ++jj) {
        int nrow = nb + jj * 16;
        bU1[jj] = sb0 + UPD_U1 + (uint32_t)nrow * W1_STR + b_off(lane, W1_STR);
        bU2[jj] = sb0 + UPD_U2 + (uint32_t)nrow * W2_STR + b_off(lane, W2_STR);
    }

    const int g = lane >> 2, tg = lane & 3;
    float acc[2][4][4];

    // t = relu([nf|agg] @ U1 + b1), K=256 uninterrupted
    zacc(acc);
    wgemm<8>(aH0, aH1, bU1, acc);
    {
        uint32_t bU1hi[2] = {bU1[0] + 256, bU1[1] + 256};
        wgemm<8>(aE0, aE1, bU1hi, acc);
    }
    __syncthreads();  // sH reads done
#pragma unroll
    for (int i = 0; i < 2; ++i) {
        int r0 = mb + i * 16 + g;
#pragma unroll
        for (int j = 0; j < 4; ++j) {
            int c = nb + j * 8 + 2 * tg;
            *reinterpret_cast<__half2*>(smem + UPD_SH + r0 * SA_STR + c * 2) =
                __floats2half2_rn(fmaxf(acc[i][j][0] + sB1[c], 0.f),
                                  fmaxf(acc[i][j][1] + sB1[c + 1], 0.f));
            *reinterpret_cast<__half2*>(smem + UPD_SH + (r0 + 8) * SA_STR + c * 2) =
                __floats2half2_rn(fmaxf(acc[i][j][2] + sB1[c], 0.f),
                                  fmaxf(acc[i][j][3] + sB1[c + 1], 0.f));
        }
    }
    __syncthreads();

    zacc(acc);
    wgemm<8>(aH0, aH1, bU2, acc);  // out = t @ U2 + b2
#pragma unroll
    for (int i = 0; i < 2; ++i) {
        int r0 = base + mb + i * 16 + g;
#pragma unroll
        for (int j = 0; j < 4; ++j) {
            int c = nb + j * 8 + 2 * tg;
            if (r0 < NN)
                *reinterpret_cast<float2*>(out + (size_t)r0 * HID + c) =
                    make_float2(acc[i][j][0] + sB2[c], acc[i][j][1] + sB2[c + 1]);
            if (r0 + 8 < NN)
                *reinterpret_cast<float2*>(out + (size_t)(r0 + 8) * HID + c) =
                    make_float2(acc[i][j][2] + sB2[c], acc[i][j][3] + sB2[c + 1]);
        }
    }
}

// ---------------------------------------------------------------------------
extern "C" void kernel_launch(void* const* d_in, const int* in_sizes, int n_in,
                              void* d_out, int out_size) {
    const float* node_feats = (const float*)d_in[0];
    const int*   edge_idx   = (const int*)d_in[1];
    const float* edge_feats = (const float*)d_in[2];
    const float* node_W     = (const float*)d_in[3];
    const float* node_b     = (const float*)d_in[4];
    const float* edge_W     = (const float*)d_in[5];
    const float* edge_b     = (const float*)d_in[6];
    const float* msg_W1     = (const float*)d_in[7];
    const float* msg_b1     = (const float*)d_in[8];
    const float* msg_W2     = (const float*)d_in[9];
    const float* msg_b2     = (const float*)d_in[10];
    const float* upd_W1     = (const float*)d_in[11];
    const float* upd_b1     = (const float*)d_in[12];
    const float* upd_W2     = (const float*)d_in[13];
    const float* upd_b2     = (const float*)d_in[14];
    float* out = (float*)d_out;

    cudaFuncSetAttribute(k_node,   cudaFuncAttributeMaxDynamicSharedMemorySize, NODE_SMEM);
    cudaFuncSetAttribute(k_edge,   cudaFuncAttributeMaxDynamicSharedMemorySize, EDGE_SMEM);
    cudaFuncSetAttribute(k_update, cudaFuncAttributeMaxDynamicSharedMemorySize, UPD_SMEM);

    const int NB_NODE = (NN + 127) / 128;  // 391
    const int NB_EDGE = NE / 128;          // 6250

    k_tW<<<128, 256>>>(node_W, edge_W, msg_W1, msg_W2, upd_W1, upd_W2);
    k_zero_agg<<<NN * HID / 4 / 256, 256>>>();
    k_node<<<NB_NODE, 512, NODE_SMEM>>>(node_feats, node_b);
    k_edge<<<NB_EDGE, 512, EDGE_SMEM>>>(edge_idx, edge_feats, edge_b, msg_b1, msg_b2);
    k_update<<<NB_NODE, 512, UPD_SMEM>>>(node_feats, upd_b1, upd_b2, out);
}

// round 11
// speedup vs baseline: 1.0757x; 1.0757x over previous
#include <cuda_runtime.h>
#include <cuda_fp16.h>
#include <cstdint>

#define HID 128
#define NN 50000
#define NE 800000
#define T_TILES 5
// byte strides (all ≡16 mod 128 -> ldmatrix conflict-free)
#define SA_STR 272   // sH / sE rows: 136 halves
#define EF_STR 144   // sEF rows: 72 halves (64 used)
#define EW_STR 144   // eWt [128 x 64k]
#define W1_STR 528   // W1t [128 x 256k]
#define W2_STR 272   // W2t [128 x 128k]

extern __shared__ char dyn_smem[];

// ---------------- device scratch (allocation-free rule) ----------------
__device__ __half g_h[(size_t)NN * HID];   // node embeddings (fp16)
__device__ float  g_agg[(size_t)NN * HID]; // segment-sum accumulator (fp32)
__device__ __half g_nWt[128 * 128];
__device__ __half g_eWt[128 * 64];
__device__ __half g_W1t[128 * 256];
__device__ __half g_W2t[128 * 128];
__device__ __half g_U1t[128 * 256];
__device__ __half g_U2t[128 * 128];

// ======================= helpers (generic PTX) =========================
__device__ __forceinline__ uint32_t smem_u32(const void* p) {
    uint32_t a;
    asm("{ .reg .u64 t; cvta.to.shared.u64 t, %1; cvt.u32.u64 %0, t; }"
        : "=r"(a) : "l"(p));
    return a;
}
__device__ __forceinline__ void ldsm4(uint32_t r[4], uint32_t addr) {
    asm volatile("ldmatrix.sync.aligned.m8n8.x4.shared.b16 {%0,%1,%2,%3}, [%4];"
                 : "=r"(r[0]), "=r"(r[1]), "=r"(r[2]), "=r"(r[3]) : "r"(addr));
}
__device__ __forceinline__ void mma16(float c[4], const uint32_t a[4],
                                      uint32_t b0, uint32_t b1) {
    asm volatile("mma.sync.aligned.m16n8k16.row.col.f32.f16.f16.f32 "
                 "{%0,%1,%2,%3}, {%4,%5,%6,%7}, {%8,%9}, {%0,%1,%2,%3};"
                 : "+f"(c[0]), "+f"(c[1]), "+f"(c[2]), "+f"(c[3])
                 : "r"(a[0]), "r"(a[1]), "r"(a[2]), "r"(a[3]), "r"(b0), "r"(b1));
}
#define CP16(dst, src) \
    asm volatile("cp.async.cg.shared.global [%0], [%1], 16;" :: "r"(dst), "l"(src))
#define CP_COMMIT() asm volatile("cp.async.commit_group;" ::: "memory")
#define CP_WAIT(n)  asm volatile("cp.async.wait_group %0;" :: "n"(n) : "memory")

__device__ __forceinline__ void zacc(float acc[2][4][4]) {
#pragma unroll
    for (int i = 0; i < 2; ++i)
#pragma unroll
        for (int j = 0; j < 4; ++j)
#pragma unroll
            for (int k = 0; k < 4; ++k) acc[i][j][k] = 0.f;
}

// Warp GEMM: 32x32 tile, KSTEPS k-steps of 16 (32B each).
template <int KSTEPS>
__device__ __forceinline__ void wgemm(uint32_t aA0, uint32_t aA1,
                                      const uint32_t bA[2], float acc[2][4][4]) {
#pragma unroll
    for (int ks = 0; ks < KSTEPS; ++ks) {
        uint32_t a0[4], a1[4];
        ldsm4(a0, aA0 + ks * 32);
        ldsm4(a1, aA1 + ks * 32);
#pragma unroll
        for (int jj = 0; jj < 2; ++jj) {
            uint32_t b[4];
            ldsm4(b, bA[jj] + ks * 32);
            mma16(acc[0][2 * jj],     a0, b[0], b[1]);
            mma16(acc[0][2 * jj + 1], a0, b[2], b[3]);
            mma16(acc[1][2 * jj],     a1, b[0], b[1]);
            mma16(acc[1][2 * jj + 1], a1, b[2], b[3]);
        }
    }
}

__device__ __forceinline__ uint32_t a_off(int lane, int strideB) {
    int row = (lane & 7) + ((lane & 8) ? 8 : 0);
    return (uint32_t)row * strideB + ((lane & 16) ? 16 : 0);
}
__device__ __forceinline__ uint32_t b_off(int lane, int strideB) {
    int row = (lane & 7) + ((lane & 16) ? 8 : 0);
    return (uint32_t)row * strideB + ((lane & 8) ? 16 : 0);
}

template <int KH>
__device__ __forceinline__ void stage_w(uint32_t dstB, int dstStr,
                                        const __half* srcBase, int srcK, int tid) {
    constexpr int SEGS = KH / 8;
#pragma unroll
    for (int i = tid; i < 128 * SEGS; i += 512) {
        int n = i / SEGS, s = i % SEGS;
        CP16(dstB + (uint32_t)(n * dstStr + s * 16),
             srcBase + (size_t)n * srcK + s * 8);
    }
}

// ---------------------------------------------------------------------------
// Prep kernels
// ---------------------------------------------------------------------------
__global__ void k_tW(const float* __restrict__ nW, const float* __restrict__ eW,
                     const float* __restrict__ W1, const float* __restrict__ W2,
                     const float* __restrict__ U1, const float* __restrict__ U2) {
    int t = blockIdx.x * blockDim.x + threadIdx.x;
    int tot = gridDim.x * blockDim.x;
    for (int i = t; i < 128 * 128; i += tot) {
        int n = i >> 7, k = i & 127;
        g_nWt[i] = __float2half_rn(nW[k * 128 + n]);
        g_W2t[i] = __float2half_rn(W2[k * 128 + n]);
        g_U2t[i] = __float2half_rn(U2[k * 128 + n]);
    }
    for (int i = t; i < 128 * 64; i += tot) {
        int n = i >> 6, k = i & 63;
        g_eWt[i] = __float2half_rn(eW[k * 128 + n]);
    }
    for (int i = t; i < 128 * 256; i += tot) {
        int n = i >> 8, k = i & 255;
        g_W1t[i] = __float2half_rn(W1[k * 128 + n]);
        g_U1t[i] = __float2half_rn(U1[k * 128 + n]);
    }
}

__global__ __launch_bounds__(256) void k_zero_agg() {
    size_t i = (size_t)blockIdx.x * 256 + threadIdx.x;
    reinterpret_cast<float4*>(g_agg)[i] = make_float4(0.f, 0.f, 0.f, 0.f);
}

// ---------------------------------------------------------------------------
// Kernel 1: h = fp16(node_feats @ node_W + node_b) -> g_h
// ---------------------------------------------------------------------------
static constexpr int NODE_SA = 0;
static constexpr int NODE_SB = 128 * SA_STR;
static constexpr int NODE_BIAS = NODE_SB + 128 * SA_STR;
static constexpr int NODE_SMEM = NODE_BIAS + 512;

__global__ __launch_bounds__(512, 1) void k_node(const float* __restrict__ nf,
                                                 const float* __restrict__ b) {
    char* smem = dyn_smem;
    float* sBias = reinterpret_cast<float*>(smem + NODE_BIAS);
    const uint32_t sb0 = smem_u32(smem);
    const int tid = threadIdx.x, lane = tid & 31, w = tid >> 5;
    const int base = blockIdx.x * 128;

    if (tid < 128) sBias[tid] = b[tid];
    for (int i = tid; i < 128 * 32; i += 512) {
        int r = i >> 5, c = (i & 31) * 4;
        int gr = base + r;
        float4 v = make_float4(0.f, 0.f, 0.f, 0.f);
        if (gr < NN) v = *reinterpret_cast<const float4*>(nf + (size_t)gr * HID + c);
        __half2* p = reinterpret_cast<__half2*>(smem + NODE_SA + r * SA_STR + c * 2);
        p[0] = __floats2half2_rn(v.x, v.y);
        p[1] = __floats2half2_rn(v.z, v.w);
    }
    for (int i = tid; i < 128 * 16; i += 512) {
        int r = i >> 4, s = (i & 15);
        *reinterpret_cast<float4*>(smem + NODE_SB + r * SA_STR + s * 16) =
            *reinterpret_cast<const float4*>(
                reinterpret_cast<const char*>(g_nWt) + (size_t)r * 256 + s * 16);
    }
    __syncthreads();

    const int mb = (w & 3) * 32, nb = (w >> 2) * 32;
    uint32_t aA0 = sb0 + NODE_SA + (uint32_t)mb * SA_STR + a_off(lane, SA_STR);
    uint32_t aA1 = aA0 + 16 * SA_STR;
    uint32_t bA[2];
#pragma unroll
    for (int jj = 0; jj < 2; ++jj)
        bA[jj] = sb0 + NODE_SB + (uint32_t)(nb + jj * 16) * SA_STR + b_off(lane, SA_STR);

    float acc[2][4][4];
    zacc(acc);
    wgemm<8>(aA0, aA1, bA, acc);

    const int g = lane >> 2, tg = lane & 3;
#pragma unroll
    for (int i = 0; i < 2; ++i) {
        int r0 = base + mb + i * 16 + g;
#pragma unroll
        for (int j = 0; j < 4; ++j) {
            int c = nb + j * 8 + 2 * tg;
            if (r0 < NN)
                *reinterpret_cast<__half2*>(g_h + (size_t)r0 * HID + c) =
                    __floats2half2_rn(acc[i][j][0] + sBias[c], acc[i][j][1] + sBias[c + 1]);
            if (r0 + 8 < NN)
                *reinterpret_cast<__half2*>(g_h + (size_t)(r0 + 8) * HID + c) =
                    __floats2half2_rn(acc[i][j][2] + sBias[c], acc[i][j][3] + sBias[c + 1]);
        }
    }
}

// ---------------------------------------------------------------------------
// Kernel 2: fused edge pipeline, 5 tiles/CTA, weights resident,
// cross-tile prefetch of ef (LDG->STS) and h-gather (cp.async).
// smem: sH | sE | sEF[2] | eW | W1 | W2 | biases
// ---------------------------------------------------------------------------
static constexpr int SH_B  = 0;
static constexpr int SE_B  = 34816;
static constexpr int EF0_B = 69632;
static constexpr int EF1_B = 88064;
static constexpr int EW_B  = 106496;
static constexpr int W1_B  = 124928;
static constexpr int W2_B  = 192512;
static constexpr int MISC_B = 227328;
static constexpr int EDGE_SMEM = MISC_B + 1536;  // 228864

__global__ __launch_bounds__(512, 1) void k_edge(const int* __restrict__ eidx,
                                                 const float* __restrict__ ef,
                                                 const float* __restrict__ eb,
                                                 const float* __restrict__ b1,
                                                 const float* __restrict__ b2) {
    char* smem = dyn_smem;
    float* sEB = reinterpret_cast<float*>(smem + MISC_B);
    float* sB1b = sEB + 128;
    float* sB2b = sB1b + 128;
    const uint32_t sb0 = smem_u32(smem);

    const int tid = threadIdx.x, lane = tid & 31, w = tid >> 5;
    const int ebase = blockIdx.x * (T_TILES * 128);

    if (tid < 128) sEB[tid] = eb[tid];
    else if (tid < 256) {
        sB1b[tid - 128] = b1[tid - 128];
        sB2b[tid - 128] = b2[tid - 128];
    }

    // ---- prologue: weights + gather(0) via cp.async; ef(0) via LDG/STS ----
    stage_w<64>(sb0 + EW_B, EW_STR, g_eWt, 64, tid);
    stage_w<256>(sb0 + W1_B, W1_STR, g_W1t, 256, tid);
    stage_w<128>(sb0 + W2_B, W2_STR, g_W2t, 128, tid);
#pragma unroll
    for (int i = tid; i < 128 * 16; i += 512) {
        int r = i >> 4, s = i & 15;
        int src = eidx[ebase + r];
        CP16(sb0 + SH_B + (uint32_t)(r * SA_STR + s * 16),
             g_h + (size_t)src * HID + s * 8);
    }
    CP_COMMIT();
#pragma unroll
    for (int i = tid; i < 128 * 16; i += 512) {
        int r = i >> 4, c = (i & 15) * 4;
        float4 v = *reinterpret_cast<const float4*>(ef + (size_t)(ebase + r) * 64 + c);
        __half2* p = reinterpret_cast<__half2*>(smem + EF0_B + r * EF_STR + c * 2);
        p[0] = __floats2half2_rn(v.x, v.y);
        p[1] = __floats2half2_rn(v.z, v.w);
    }
    CP_WAIT(0);
    __syncthreads();

    const int mb = (w & 3) * 32, nb = (w >> 2) * 32;
    uint32_t aH0 = sb0 + SH_B + (uint32_t)mb * SA_STR + a_off(lane, SA_STR);
    uint32_t aH1 = aH0 + 16 * SA_STR;
    uint32_t aS0 = sb0 + SE_B + (uint32_t)mb * SA_STR + a_off(lane, SA_STR);
    uint32_t aS1 = aS0 + 16 * SA_STR;
    uint32_t aF0[2], aF1[2];
    aF0[0] = sb0 + EF0_B + (uint32_t)mb * EF_STR + a_off(lane, EF_STR);
    aF1[0] = aF0[0] + 16 * EF_STR;
    aF0[1] = aF0[0] + (EF1_B - EF0_B);
    aF1[1] = aF1[0] + (EF1_B - EF0_B);
    uint32_t bEW[2], bW1[2], bW2[2];
#pragma unroll
    for (int jj = 0; jj < 2; ++jj) {
        int nrow = nb + jj * 16;
        bEW[jj] = sb0 + EW_B + (uint32_t)nrow * EW_STR + b_off(lane, EW_STR);
        bW1[jj] = sb0 + W1_B + (uint32_t)nrow * W1_STR + b_off(lane, W1_STR);
        bW2[jj] = sb0 + W2_B + (uint32_t)nrow * W2_STR + b_off(lane, W2_STR);
    }

    const int g = lane >> 2, tg = lane & 3;
    float acc[2][4][4];

#pragma unroll 1
    for (int t = 0; t < T_TILES; ++t) {
        const int e0 = ebase + t * 128;
        const int cur = t & 1, nxt = cur ^ 1;
        const bool pf = (t + 1 < T_TILES);

        // ---- GEMM0: e = ef @ eWt (K=64), A = sEF[cur] ----
        zacc(acc);
        wgemm<4>(aF0[cur], aF1[cur], bEW, acc);

        // prefetch ef(t+1): LDG fp32 (4x float4/thread)
        float4 efr[4];
        if (pf) {
#pragma unroll
            for (int j = 0; j < 4; ++j) {
                int idx = tid + j * 512;
                int r = idx >> 4, c = (idx & 15) * 4;
                efr[j] = *reinterpret_cast<const float4*>(
                    ef + (size_t)(e0 + 128 + r) * 64 + c);
            }
        }

        // epilogue0: e = acc + eb -> sE (sE free: GEMM2(t-1) done + synced)
#pragma unroll
        for (int i = 0; i < 2; ++i) {
            int r0 = mb + i * 16 + g;
#pragma unroll
            for (int j = 0; j < 4; ++j) {
                int c = nb + j * 8 + 2 * tg;
                *reinterpret_cast<__half2*>(smem + SE_B + r0 * SA_STR + c * 2) =
                    __floats2half2_rn(acc[i][j][0] + sEB[c], acc[i][j][1] + sEB[c + 1]);
                *reinterpret_cast<__half2*>(smem + SE_B + (r0 + 8) * SA_STR + c * 2) =
                    __floats2half2_rn(acc[i][j][2] + sEB[c], acc[i][j][3] + sEB[c + 1]);
            }
        }
        // STS ef(t+1) -> sEF[nxt] (last read at GEMM0(t-1); safe)
        if (pf) {
            uint32_t efb = (nxt ? EF1_B : EF0_B);
#pragma unroll
            for (int j = 0; j < 4; ++j) {
                int idx = tid + j * 512;
                int r = idx >> 4, c = (idx & 15) * 4;
                __half2* p = reinterpret_cast<__half2*>(smem + efb + r * EF_STR + c * 2);
                p[0] = __floats2half2_rn(efr[j].x, efr[j].y);
                p[1] = __floats2half2_rn(efr[j].z, efr[j].w);
            }
        }
        __syncthreads();  // publish e (+ ef STS)

        // ---- GEMM1: t = [h|e] @ W1 (K=256, uninterrupted) ----
        zacc(acc);
        wgemm<8>(aH0, aH1, bW1, acc);
        {
            uint32_t bW1hi[2] = {bW1[0] + 256, bW1[1] + 256};
            wgemm<8>(aS0, aS1, bW1hi, acc);
        }
        __syncthreads();  // sH + sE reads done

        // epilogue1: t = relu(acc + b1) -> sE ; gather(t+1) -> sH (cp.async)
        if (pf) {
#pragma unroll
            for (int i = tid; i < 128 * 16; i += 512) {
                int r = i >> 4, s = i & 15;
                int src = eidx[e0 + 128 + r];
                CP16(sb0 + SH_B + (uint32_t)(r * SA_STR + s * 16),
                     g_h + (size_t)src * HID + s * 8);
            }
            CP_COMMIT();
        }
#pragma unroll
        for (int i = 0; i < 2; ++i) {
            int r0 = mb + i * 16 + g;
#pragma unroll
            for (int j = 0; j < 4; ++j) {
                int c = nb + j * 8 + 2 * tg;
                *reinterpret_cast<__half2*>(smem + SE_B + r0 * SA_STR + c * 2) =
                    __floats2half2_rn(fmaxf(acc[i][j][0] + sB1b[c], 0.f),
                                      fmaxf(acc[i][j][1] + sB1b[c + 1], 0.f));
                *reinterpret_cast<__half2*>(smem + SE_B + (r0 + 8) * SA_STR + c * 2) =
                    __floats2half2_rn(fmaxf(acc[i][j][2] + sB1b[c], 0.f),
                                      fmaxf(acc[i][j][3] + sB1b[c + 1], 0.f));
            }
        }
        __syncthreads();  // publish t

        // ---- GEMM2: m = t @ W2 (K=128), A = sE ----
        zacc(acc);
        wgemm<8>(aS0, aS1, bW2, acc);

        // scatter-add into g_agg[dst]
#pragma unroll
        for (int i = 0; i < 2; ++i) {
            int r0 = mb + i * 16 + g;
            int d0 = eidx[NE + e0 + r0];
            int d1 = eidx[NE + e0 + r0 + 8];
            float* p0 = g_agg + (size_t)d0 * HID;
            float* p1 = g_agg + (size_t)d1 * HID;
#pragma unroll
            for (int j = 0; j < 4; ++j) {
                int c = nb + j * 8 + 2 * tg;
                atomicAdd(p0 + c, acc[i][j][0] + sB2b[c]);
                atomicAdd(p0 + c + 1, acc[i][j][1] + sB2b[c + 1]);
                atomicAdd(p1 + c, acc[i][j][2] + sB2b[c]);
                atomicAdd(p1 + c + 1, acc[i][j][3] + sB2b[c + 1]);
            }
        }
        CP_WAIT(0);
        __syncthreads();  // publish gather(t+1); GEMM2 sE reads done (WAR)
    }
}

// ---------------------------------------------------------------------------
// Kernel 3: out = relu([nf|agg] @ U1 + ub1) @ U2 + ub2
// ---------------------------------------------------------------------------
static constexpr int UPD_SH = 0;
static constexpr int UPD_SE = 128 * SA_STR;
static constexpr int UPD_U1 = 2 * 128 * SA_STR;
static constexpr int UPD_U2 = UPD_U1 + 128 * W1_STR;
static constexpr int UPD_B1 = UPD_U2 + 128 * W2_STR;
static constexpr int UPD_B2 = UPD_B1 + 512;
static constexpr int UPD_SMEM = UPD_B2 + 512;

__global__ __launch_bounds__(512, 1) void k_update(const float* __restrict__ nf,
                                                   const float* __restrict__ b1,
                                                   const float* __restrict__ b2,
                                                   float* __restrict__ out) {
    char* smem = dyn_smem;
    float* sB1 = reinterpret_cast<float*>(smem + UPD_B1);
    float* sB2 = reinterpret_cast<float*>(smem + UPD_B2);
    const uint32_t sb0 = smem_u32(smem);

    const int tid = threadIdx.x, lane = tid & 31, w = tid >> 5;
    const int base = blockIdx.x * 128;

    if (tid < 128) {
        sB1[tid] = b1[tid];
        sB2[tid] = b2[tid];
    }
    stage_w<256>(sb0 + UPD_U1, W1_STR, g_U1t, 256, tid);
    stage_w<128>(sb0 + UPD_U2, W2_STR, g_U2t, 128, tid);
    CP_COMMIT();

    for (int i = tid; i < 128 * 32; i += 512) {
        int r = i >> 5, c = (i & 31) * 4;
        int gr = base + r;
        float4 v0 = make_float4(0.f, 0.f, 0.f, 0.f), v1 = v0;
        if (gr < NN) {
            v0 = *reinterpret_cast<const float4*>(nf + (size_t)gr * HID + c);
            v1 = *reinterpret_cast<const float4*>(g_agg + (size_t)gr * HID + c);
        }
        __half2* p0 = reinterpret_cast<__half2*>(smem + UPD_SH + r * SA_STR + c * 2);
        p0[0] = __floats2half2_rn(v0.x, v0.y);
        p0[1] = __floats2half2_rn(v0.z, v0.w);
        __half2* p1 = reinterpret_cast<__half2*>(smem + UPD_SE + r * SA_STR + c * 2);
        p1[0] = __floats2half2_rn(v1.x, v1.y);
        p1[1] = __floats2half2_rn(v1.z, v1.w);
    }
    CP_WAIT(0);
    __syncthreads();

    const int mb = (w & 3) * 32, nb = (w >> 2) * 32;
    uint32_t aH0 = sb0 + UPD_SH + (uint32_t)mb * SA_STR + a_off(lane, SA_STR);
    uint32_t aH1 = aH0 + 16 * SA_STR;
    uint32_t aE0 = sb0 + UPD_SE + (uint32_t)mb * SA_STR + a_off(lane, SA_STR);
    uint32_t aE1 = aE0 + 16 * SA_STR;
    uint32_t bU1[2], bU2[2];
#pragma unroll
    for (int jj = 0; jj < 2; ++jj) {
        int nrow = nb + jj * 16;
        bU1[jj] = sb0 + UPD_U1 + (uint32_t)nrow * W1_STR + b_off(lane, W1_STR);
        bU2[jj] = sb0 + UPD_U2 + (uint32_t)nrow * W2_STR + b_off(lane, W2_STR);
    }

    const int g = lane >> 2, tg = lane & 3;
    float acc[2][4][4];

    zacc(acc);
    wgemm<8>(aH0, aH1, bU1, acc);
    {
        uint32_t bU1hi[2] = {bU1[0] + 256, bU1[1] + 256};
        wgemm<8>(aE0, aE1, bU1hi, acc);
    }
    __syncthreads();
#pragma unroll
    for (int i = 0; i < 2; ++i) {
        int r0 = mb + i * 16 + g;
#pragma unroll
        for (int j = 0; j < 4; ++j) {
            int c = nb + j * 8 + 2 * tg;
            *reinterpret_cast<__half2*>(smem + UPD_SH + r0 * SA_STR + c * 2) =
                __floats2half2_rn(fmaxf(acc[i][j][0] + sB1[c], 0.f),
                                  fmaxf(acc[i][j][1] + sB1[c + 1], 0.f));
            *reinterpret_cast<__half2*>(smem + UPD_SH + (r0 + 8) * SA_STR + c * 2) =
                __floats2half2_rn(fmaxf(acc[i][j][2] + sB1[c], 0.f),
                                  fmaxf(acc[i][j][3] + sB1[c + 1], 0.f));
        }
    }
    __syncthreads();

    zacc(acc);
    wgemm<8>(aH0, aH1, bU2, acc);
#pragma unroll
    for (int i = 0; i < 2; ++i) {
        int r0 = base + mb + i * 16 + g;
#pragma unroll
        for (int j = 0; j < 4; ++j) {
            int c = nb + j * 8 + 2 * tg;
            if (r0 < NN)
                *reinterpret_cast<float2*>(out + (size_t)r0 * HID + c) =
                    make_float2(acc[i][j][0] + sB2[c], acc[i][j][1] + sB2[c + 1]);
            if (r0 + 8 < NN)
                *reinterpret_cast<float2*>(out + (size_t)(r0 + 8) * HID + c) =
                    make_float2(acc[i][j][2] + sB2[c], acc[i][j][3] + sB2[c + 1]);
        }
    }
}

// ---------------------------------------------------------------------------
extern "C" void kernel_launch(void* const* d_in, const int* in_sizes, int n_in,
                              void* d_out, int out_size) {
    const float* node_feats = (const float*)d_in[0];
    const int*   edge_idx   = (const int*)d_in[1];
    const float* edge_feats = (const float*)d_in[2];
    const float* node_W     = (const float*)d_in[3];
    const float* node_b     = (const float*)d_in[4];
    const float* edge_W     = (const float*)d_in[5];
    const float* edge_b     = (const float*)d_in[6];
    const float* msg_W1     = (const float*)d_in[7];
    const float* msg_b1     = (const float*)d_in[8];
    const float* msg_W2     = (const float*)d_in[9];
    const float* msg_b2     = (const float*)d_in[10];
    const float* upd_W1     = (const float*)d_in[11];
    const float* upd_b1     = (const float*)d_in[12];
    const float* upd_W2     = (const float*)d_in[13];
    const float* upd_b2     = (const float*)d_in[14];
    float* out = (float*)d_out;

    cudaFuncSetAttribute(k_node,   cudaFuncAttributeMaxDynamicSharedMemorySize, NODE_SMEM);
    cudaFuncSetAttribute(k_edge,   cudaFuncAttributeMaxDynamicSharedMemorySize, EDGE_SMEM);
    cudaFuncSetAttribute(k_update, cudaFuncAttributeMaxDynamicSharedMemorySize, UPD_SMEM);

    const int NB_NODE = (NN + 127) / 128;          // 391
    const int NB_EDGE = NE / (128 * T_TILES);      // 1250

    k_tW<<<128, 256>>>(node_W, edge_W, msg_W1, msg_W2, upd_W1, upd_W2);
    k_zero_agg<<<NN * HID / 4 / 256, 256>>>();
    k_node<<<NB_NODE, 512, NODE_SMEM>>>(node_feats, node_b);
    k_edge<<<NB_EDGE, 512, EDGE_SMEM>>>(edge_idx, edge_feats, edge_b, msg_b1, msg_b2);
    k_update<<<NB_NODE, 512, UPD_SMEM>>>(node_feats, upd_b1, upd_b2, out);
}